// round 2
// baseline (speedup 1.0000x reference)
#include <cuda_runtime.h>
#include <math_constants.h>

// ZBL repulsion: sum over 6.4M edges of screened Coulomb pair energy.
// Strategy: pack atoms (x,y,z,Zf) -> float4 table (fits L2), pow-table for
// Z^a_exp, int4-vectorized index streaming, skip MUFU tail when cutoff==0,
// hierarchical reduction into a double accumulator.

static constexpr int MAX_ATOMS = 131072;
static constexpr float R_MAX = 6.0f;

__device__ float4 g_atoms[MAX_ATOMS];
__device__ float  g_powtab[64];
__device__ double g_acc;

// ---------------------------------------------------------------------------
__global__ void init_kernel(const float* __restrict__ a_exp) {
    int t = threadIdx.x;
    if (t < 64) g_powtab[t] = powf((float)t, a_exp[0]);
    if (t == 0) g_acc = 0.0;
}

__global__ void pack_atoms_kernel(const float* __restrict__ R,
                                  const int* __restrict__ Z, int n) {
    int i = blockIdx.x * blockDim.x + threadIdx.x;
    if (i < n) {
        g_atoms[i] = make_float4(R[3 * i + 0], R[3 * i + 1], R[3 * i + 2],
                                 (float)Z[i]);
    }
}

// ---------------------------------------------------------------------------
__device__ __forceinline__ float edge_energy(int ia, int ja, int n_atoms,
                                             float inv_anum,
                                             float c0, float c1, float c2, float c3,
                                             float e0, float e1, float e2, float e3,
                                             const float* __restrict__ s_pow) {
    if ((unsigned)ia >= (unsigned)n_atoms || (unsigned)ja >= (unsigned)n_atoms)
        return 0.0f;
    float4 Ai = g_atoms[ia];
    float4 Aj = g_atoms[ja];
    float dx = Aj.x - Ai.x;
    float dy = Aj.y - Ai.y;
    float dz = Aj.z - Ai.z;
    float r2 = fmaf(dx, dx, fmaf(dy, dy, dz * dz));
    float dr = sqrtf(r2);
    dr = fmaxf(dr, 0.02f);
    float res = 0.0f;
    if (dr < R_MAX) {  // cutoff is exactly 0 at dr >= R_MAX
        float cut = 0.5f * (__cosf(dr * (CUDART_PI_F / R_MAX)) + 1.0f);
        float zp  = s_pow[(int)Ai.w] + s_pow[(int)Aj.w];
        float dist = dr * zp * inv_anum;
        float f = c0 * __expf(-e0 * dist);
        f = fmaf(c1, __expf(-e1 * dist), f);
        f = fmaf(c2, __expf(-e2 * dist), f);
        f = fmaf(c3, __expf(-e3 * dist), f);
        res = 0.5f * Ai.w * Aj.w * __fdividef(f * cut, dr);
    }
    return res;
}

__global__ void __launch_bounds__(256)
edge_kernel(const int* __restrict__ idx, int E, int n_atoms,
            const float* __restrict__ a_num,
            const float* __restrict__ coef,
            const float* __restrict__ expo) {
    __shared__ float s_pow[64];
    __shared__ float s_red[8];

    int t = threadIdx.x;
    if (t < 64) s_pow[t] = g_powtab[t];
    __syncthreads();

    float inv_anum = __fdividef(1.0f, __ldg(a_num));
    float c0 = __ldg(coef + 0), c1 = __ldg(coef + 1);
    float c2 = __ldg(coef + 2), c3 = __ldg(coef + 3);
    float e0 = __ldg(expo + 0), e1 = __ldg(expo + 1);
    float e2 = __ldg(expo + 2), e3 = __ldg(expo + 3);

    int nvec = E >> 2;  // int4 chunks
    const int4* __restrict__ ii = (const int4*)idx;
    const int4* __restrict__ jj = (const int4*)(idx + E);

    float acc = 0.0f;
    int v = blockIdx.x * blockDim.x + t;
    if (v < nvec) {
        int4 a = __ldg(ii + v);
        int4 b = __ldg(jj + v);
        acc += edge_energy(a.x, b.x, n_atoms, inv_anum, c0, c1, c2, c3, e0, e1, e2, e3, s_pow);
        acc += edge_energy(a.y, b.y, n_atoms, inv_anum, c0, c1, c2, c3, e0, e1, e2, e3, s_pow);
        acc += edge_energy(a.z, b.z, n_atoms, inv_anum, c0, c1, c2, c3, e0, e1, e2, e3, s_pow);
        acc += edge_energy(a.w, b.w, n_atoms, inv_anum, c0, c1, c2, c3, e0, e1, e2, e3, s_pow);
    }
    // tail edges (E not multiple of 4) handled by global thread 0
    if (v == 0) {
        for (int e = nvec << 2; e < E; e++) {
            acc += edge_energy(idx[e], idx[E + e], n_atoms, inv_anum,
                               c0, c1, c2, c3, e0, e1, e2, e3, s_pow);
        }
    }

    // warp reduce
    #pragma unroll
    for (int o = 16; o > 0; o >>= 1)
        acc += __shfl_down_sync(0xFFFFFFFFu, acc, o);
    int lane = t & 31, wid = t >> 5;
    if (lane == 0) s_red[wid] = acc;
    __syncthreads();
    if (wid == 0) {
        float vsum = (t < 8) ? s_red[t] : 0.0f;
        #pragma unroll
        for (int o = 4; o > 0; o >>= 1)
            vsum += __shfl_down_sync(0xFFFFFFFFu, vsum, o);
        if (t == 0) atomicAdd(&g_acc, (double)vsum);
    }
}

__global__ void writeback_kernel(float* __restrict__ out) {
    out[0] = (float)g_acc;
}

// ---------------------------------------------------------------------------
extern "C" void kernel_launch(void* const* d_in, const int* in_sizes, int n_in,
                              void* d_out, int out_size) {
    const float* R     = (const float*)d_in[0];
    const int*   Z     = (const int*)d_in[1];
    const int*   idx   = (const int*)d_in[2];
    const float* a_exp = (const float*)d_in[3];
    const float* a_num = (const float*)d_in[4];
    const float* coef  = (const float*)d_in[5];
    const float* expo  = (const float*)d_in[6];
    float* out = (float*)d_out;

    int n_atoms = in_sizes[1];
    int E = in_sizes[2] / 2;

    init_kernel<<<1, 64>>>(a_exp);
    int pb = (n_atoms + 255) / 256;
    pack_atoms_kernel<<<pb, 256>>>(R, Z, n_atoms);

    int nvec = E >> 2;
    int blocks = (nvec + 255) / 256;
    if (blocks < 1) blocks = 1;
    edge_kernel<<<blocks, 256>>>(idx, E, n_atoms, a_num, coef, expo);
    writeback_kernel<<<1, 1>>>(out);
}